// round 11
// baseline (speedup 1.0000x reference)
#include <cuda_runtime.h>
#include <math.h>

// ---------------- problem constants ----------------
#define BATCH   32
#define CIN     256
#define COUT    64
#define HW      1024
#define NE      1024
#define EDIM    64
#define NROWS   32768
#define ZLEN    (BATCH*COUT*HW)   // 2097152
#define TILES   8
#define CODE_TILE 128
#define ROWS_BLK 80               // rows per argmin block (16 groups x RPT)
#define RPT      5                // rows per thread
#define NBLK     410              // ceil(32768/80); last block 48 valid rows

// output layout (concat, float32): z_q | loss | sampled | min_idx
#define ZQ_OFF   0
#define LOSS_OFF ((size_t)ZLEN)
#define SAMP_OFF ((size_t)ZLEN + 1)
#define MIDX_OFF ((size_t)ZLEN + 1 + NROWS)

// argmin smem (single-buffered e): zs4[80*17] | es4[64*33] | Sz[80] | se[128] | red[256]
#define ZS_F4    (ROWS_BLK * 17)          // 1360
#define ES_F4    (64 * 33)                // 2112
#define SMEM_ARGMIN ((ZS_F4 + ES_F4) * 16 + ROWS_BLK * 4 + 128 * 4 + 256 * 4)  // 57408

// ---------------- device scratch ----------------
__device__ __align__(16) float g_z[ZLEN];
__device__ __align__(16) float g_embi[NE * EDIM];   // pair-interleaved codebook
__device__ int   g_idx[NROWS];
__device__ float g_se[NE];
__device__ float g_loss_part[NBLK];
__device__ float g_s_part[32 * EDIM];
__device__ int   g_done;

// ---------------- packed f32x2 helpers (bit-exact per-lane fma.rn) ----------------
__device__ __forceinline__ unsigned long long dupf(float v) {
    unsigned long long r;
    asm("mov.b64 %0, {%1, %1};" : "=l"(r) : "r"(__float_as_uint(v)));
    return r;
}
__device__ __forceinline__ unsigned long long pack2(float a, float b) {
    unsigned long long r;
    asm("mov.b64 %0, {%1, %2};" : "=l"(r) : "r"(__float_as_uint(a)), "r"(__float_as_uint(b)));
    return r;
}
__device__ __forceinline__ void fma2(unsigned long long& d,
                                     unsigned long long a, unsigned long long b) {
    asm("fma.rn.f32x2 %0, %1, %2, %0;" : "+l"(d) : "l"(a), "l"(b));
}
__device__ __forceinline__ void unpack2(float& lo, float& hi, unsigned long long v) {
    asm("mov.b64 {%0, %1}, %2;" : "=f"(lo), "=f"(hi) : "l"(v));
}

// Replicated XLA-CPU reduce order: VF=4, IC=2, fmla, faddp-adjacent horizontal.
__device__ __forceinline__ float sumsq64_p(const float4* v4) {
    float a0=0.f,a1=0.f,a2=0.f,a3=0.f, b0=0.f,b1=0.f,b2=0.f,b3=0.f;
    #pragma unroll
    for (int t = 0; t < 8; t++) {
        float4 x = v4[2*t];
        a0 = __fmaf_rn(x.x, x.x, a0); a1 = __fmaf_rn(x.y, x.y, a1);
        a2 = __fmaf_rn(x.z, x.z, a2); a3 = __fmaf_rn(x.w, x.w, a3);
        float4 y = v4[2*t+1];
        b0 = __fmaf_rn(y.x, y.x, b0); b1 = __fmaf_rn(y.y, y.y, b1);
        b2 = __fmaf_rn(y.z, y.z, b2); b3 = __fmaf_rn(y.w, y.w, b3);
    }
    float L0 = a0 + b0, L1 = a1 + b1, L2 = a2 + b2, L3 = a3 + b3;
    return (L0 + L1) + (L2 + L3);
}

// ============================================================
// K1: fused prep (codebook interleave) + norms/contrastive + sampled-zero
//     + 1x1 conv (register-tiled, FMA2, bitwise Eigen order).
// Pair layout (128-code tiles): pair-row r = q*16+s holds codes
// (t*128 + 8s + 2q, +1), element-interleaved by k.
// ============================================================
__global__ void __launch_bounds__(128) k_conv(const float* __restrict__ zin,
                                              const float* __restrict__ w,
                                              const float* __restrict__ bias,
                                              const float* __restrict__ emb,
                                              float* __restrict__ out) {
    __shared__ unsigned long long ws[CIN * 8];
    __shared__ float bs[16];
    __shared__ float inv_n[32];
    __shared__ float sq[2][EDIM];

    int tid = threadIdx.x;
    int blk = blockIdx.x;

    // ---- prep: pair-interleave codebook (2 elements per thread) ----
    #pragma unroll
    for (int e = 0; e < 2; e++) {
        int o = blk * 256 + e * 128 + tid;
        int P = o >> 7, r = o & 127;
        int k = r >> 1, l = r & 1;
        int t = P >> 6, rem = P & 63;
        int q = rem >> 4, sl = rem & 15;
        int j = t * 128 + 8 * sl + 2 * q + l;
        g_embi[o] = emb[(size_t)j * EDIM + k];
    }
    // zero 'sampled' region (1:1 thread map) + reset completion counter
    out[SAMP_OFF + blk * 128 + tid] = 0.0f;
    if (blk == 0 && tid == 0) g_done = 0;

    // ---- norms + contrastive partials (blocks 0..31) ----
    if (blk < 32) {
        if (tid < 32) {
            int i = blk * 32 + tid;
            float v = sumsq64_p((const float4*)(emb + (size_t)i * EDIM));
            g_se[i] = v;
            inv_n[tid] = 1.0f / sqrtf(v);
        }
        __syncthreads();
        int k = tid & 63, q = tid >> 6;
        float sacc = 0.f;
        #pragma unroll
        for (int i = 0; i < 16; i++) {
            int code = q * 16 + i;
            sacc += emb[(size_t)(blk * 32 + code) * EDIM + k] * inv_n[code];
        }
        sq[q][k] = sacc;
        __syncthreads();
        if (tid < EDIM)
            g_s_part[blk * EDIM + tid] = sq[0][tid] + sq[1][tid];
    }
    __syncthreads();

    // ---- conv ----
    int b = blk >> 3, half = (blk >> 2) & 1, og = blk & 3;
    int obase = og * 16;

    for (int m = tid; m < CIN * 8; m += 128) {
        int c = m >> 3, u = m & 7;
        const float* wp = w + (size_t)(obase + 2 * u) * CIN + c;
        ws[m] = pack2(wp[0], wp[CIN]);
    }
    if (tid < 16) bs[tid] = bias[obase + tid];
    __syncthreads();

    int p0 = half * 512 + tid;
    const float* zp = zin + (size_t)b * CIN * HW + p0;

    unsigned long long acc[8][4];
    #pragma unroll
    for (int u = 0; u < 8; u++)
        #pragma unroll
        for (int j = 0; j < 4; j++) acc[u][j] = 0ULL;

    float zn[4][8];
    #pragma unroll
    for (int j = 0; j < 4; j++)
        #pragma unroll
        for (int i = 0; i < 8; i++)
            zn[j][i] = zp[(size_t)i * HW + 128 * j];

    const ulonglong2* ws2 = (const ulonglong2*)ws;
    for (int ch = 0; ch < 32; ch++) {
        float zc[4][8];
        #pragma unroll
        for (int j = 0; j < 4; j++)
            #pragma unroll
            for (int i = 0; i < 8; i++) zc[j][i] = zn[j][i];
        if (ch < 31) {
            #pragma unroll
            for (int j = 0; j < 4; j++)
                #pragma unroll
                for (int i = 0; i < 8; i++)
                    zn[j][i] = zp[(size_t)((ch + 1) * 8 + i) * HW + 128 * j];
        }
        #pragma unroll
        for (int cc = 0; cc < 8; cc++) {
            int c = ch * 8 + cc;
            unsigned long long zz[4];
            #pragma unroll
            for (int j = 0; j < 4; j++) zz[j] = dupf(zc[j][cc]);
            const ulonglong2* wrow = ws2 + c * 4;
            #pragma unroll
            for (int uu = 0; uu < 4; uu++) {
                ulonglong2 wp = wrow[uu];
                #pragma unroll
                for (int j = 0; j < 4; j++) {
                    fma2(acc[2*uu][j],     zz[j], wp.x);
                    fma2(acc[2*uu + 1][j], zz[j], wp.y);
                }
            }
        }
    }

    float* zo = g_z + (size_t)b * COUT * HW;
    #pragma unroll
    for (int u = 0; u < 8; u++) {
        int o = obase + 2 * u;
        #pragma unroll
        for (int j = 0; j < 4; j++) {
            float lo, hi;
            unpack2(lo, hi, acc[u][j]);
            zo[(size_t)o * HW + p0 + 128 * j]       = lo + bs[2*u];
            zo[(size_t)(o + 1) * HW + p0 + 128 * j] = hi + bs[2*u + 1];
        }
    }
}

// ============================================================
// K2: fused distance+argmin + scatter + loss (last-block finalize).
// 5 rows x 4 code-pairs per thread, 80 rows/block, grid 410, occ 3,
// 128-code single-buffered tiles. d_j = fl( fl(Sz+Se_j) - 2*dot_j ),
// dot = in-order 64-term FMA chain per lane.
// ============================================================
__global__ void __launch_bounds__(256, 3) k_argmin(float* __restrict__ out,
                                                   const float* __restrict__ emb) {
    extern __shared__ __align__(16) char smem[];
    float4* zs4  = (float4*)smem;                  // [80][17]
    float4* es4  = zs4 + ZS_F4;                    // [64 pair-rows][33]
    float*  Sz_s = (float*)(es4 + ES_F4);          // [80]
    float*  se_s = Sz_s + ROWS_BLK;                // [128]
    float*  red  = se_s + 128;                     // [256]
    __shared__ int    is_last;
    __shared__ double rd[256];
    __shared__ float  sv[EDIM];

    int tid = threadIdx.x;
    int s   = tid & 15;                            // code sublane 0..15
    int g   = tid >> 4;                            // row group 0..15
    int row0 = blockIdx.x * ROWS_BLK;

    // stage z rows (clamped for last block)
    {
        const float4* zall = (const float4*)g_z;
        #pragma unroll
        for (int j = 0; j < RPT; j++) {
            int idx = tid + 256 * j;               // 0..1279
            int r = idx >> 4, k4 = idx & 15;
            int grow = row0 + r;
            if (grow > NROWS - 1) grow = NROWS - 1;
            zs4[r * 17 + k4] = zall[(size_t)grow * 16 + k4];
        }
    }
    __syncthreads();
    if (tid < ROWS_BLK)
        Sz_s[tid] = sumsq64_p(zs4 + tid * 17);

    float best[RPT];
    int   bi[RPT];
    #pragma unroll
    for (int i = 0; i < RPT; i++) { best[i] = 3.4e38f; bi[i] = 0; }

    const float4* gsrc = (const float4*)g_embi;
    const float2* zb = ((const float2*)zs4) + g * 34;
    const ulonglong2* ebase = ((const ulonglong2*)es4) + s * 33;

    for (int t = 0; t < TILES; t++) {
        __syncthreads();      // prior tile's reads complete (and Sz on t=0)
        {
            const float4* src = gsrc + (size_t)t * 2048;
            #pragma unroll
            for (int j = 0; j < 8; j++) {
                int idx = tid + 256 * j;
                int pr = idx >> 5, wv = idx & 31;
                es4[pr * 33 + wv] = src[idx];
            }
            if (tid < CODE_TILE) se_s[tid] = g_se[t * CODE_TILE + tid];
        }
        __syncthreads();

        unsigned long long acc[RPT][4];
        #pragma unroll
        for (int i = 0; i < RPT; i++)
            #pragma unroll
            for (int q = 0; q < 4; q++) acc[i][q] = 0ULL;

        #pragma unroll 4
        for (int k4 = 0; k4 < 16; k4++) {
            // half A: dims 4k4, 4k4+1 — load the 4 e-pairs once, stream rows
            {
                ulonglong2 e0 = ebase[0 * 528 + 2 * k4];
                ulonglong2 e1 = ebase[1 * 528 + 2 * k4];
                ulonglong2 e2 = ebase[2 * 528 + 2 * k4];
                ulonglong2 e3 = ebase[3 * 528 + 2 * k4];
                #pragma unroll
                for (int i = 0; i < RPT; i++) {
                    float2 h = zb[544 * i + 2 * k4];
                    unsigned long long zx = dupf(h.x), zy = dupf(h.y);
                    fma2(acc[i][0], zx, e0.x); fma2(acc[i][0], zy, e0.y);
                    fma2(acc[i][1], zx, e1.x); fma2(acc[i][1], zy, e1.y);
                    fma2(acc[i][2], zx, e2.x); fma2(acc[i][2], zy, e2.y);
                    fma2(acc[i][3], zx, e3.x); fma2(acc[i][3], zy, e3.y);
                }
            }
            // half B: dims 4k4+2, 4k4+3
            {
                ulonglong2 e0 = ebase[0 * 528 + 2 * k4 + 1];
                ulonglong2 e1 = ebase[1 * 528 + 2 * k4 + 1];
                ulonglong2 e2 = ebase[2 * 528 + 2 * k4 + 1];
                ulonglong2 e3 = ebase[3 * 528 + 2 * k4 + 1];
                #pragma unroll
                for (int i = 0; i < RPT; i++) {
                    float2 h = zb[544 * i + 2 * k4 + 1];
                    unsigned long long zx = dupf(h.x), zy = dupf(h.y);
                    fma2(acc[i][0], zx, e0.x); fma2(acc[i][0], zy, e0.y);
                    fma2(acc[i][1], zx, e1.x); fma2(acc[i][1], zy, e1.y);
                    fma2(acc[i][2], zx, e2.x); fma2(acc[i][2], zy, e2.y);
                    fma2(acc[i][3], zx, e3.x); fma2(acc[i][3], zy, e3.y);
                }
            }
        }

        // eval: per row, q ascending -> codes 8s+2q, 8s+2q+1 ascending
        #pragma unroll
        for (int q = 0; q < 4; q++) {
            int jlo = 8 * s + 2 * q, jhi = jlo + 1;
            float selo = se_s[jlo], sehi = se_s[jhi];
            #pragma unroll
            for (int i = 0; i < RPT; i++) {
                float Szv = Sz_s[g + 16 * i];
                float dlo, dhi;
                unpack2(dlo, dhi, acc[i][q]);
                float dv = __fmaf_rn(-2.0f, dlo, Szv + selo);
                if (dv < best[i]) { best[i] = dv; bi[i] = t * CODE_TILE + jlo; }
                float dw = __fmaf_rn(-2.0f, dhi, Szv + sehi);
                if (dw < best[i]) { best[i] = dw; bi[i] = t * CODE_TILE + jhi; }
            }
        }
    }

    // lexicographic merge across the 16 sublanes (per row)
    unsigned m = 0xffffffffu;
    #pragma unroll
    for (int i = 0; i < RPT; i++) {
        float bv = best[i]; int bj = bi[i];
        #pragma unroll
        for (int off = 8; off > 0; off >>= 1) {
            float ob = __shfl_down_sync(m, bv, off, 16);
            int   oi = __shfl_down_sync(m, bj, off, 16);
            if (ob < bv || (ob == bv && oi < bj)) { bv = ob; bj = oi; }
        }
        bj = __shfl_sync(m, bj, 0, 16);
        bi[i] = bj;
    }

    // epilogue per valid row: idx/min_idx/scatter, z_q_st, loss partial
    float lacc = 0.f;
    #pragma unroll
    for (int i = 0; i < RPT; i++) {
        int rl = g + 16 * i;
        int row = row0 + rl;
        if (row < NROWS) {
            int bj = bi[i];
            if (s == 0) {
                g_idx[row] = bj;
                out[MIDX_OFF + row] = (float)bj;
                out[SAMP_OFF + bj] = 1.0f;   // sampled scatter (zeroed by k_conv)
            }
            float4 e = ((const float4*)(emb + (size_t)bj * EDIM))[s];
            float4 z = zs4[rl * 17 + s];
            float dx = e.x - z.x, dy = e.y - z.y, dz = e.z - z.z, dw = e.w - z.w;
            float4 o;
            o.x = z.x + dx; o.y = z.y + dy; o.z = z.z + dz; o.w = z.w + dw;
            ((float4*)(out + ZQ_OFF + (size_t)row * EDIM))[s] = o;
            lacc += dx*dx + dy*dy + dz*dz + dw*dw;
        }
    }
    red[tid] = lacc;
    __syncthreads();
    #pragma unroll
    for (int st = 128; st > 0; st >>= 1) {
        if (tid < st) red[tid] += red[tid + st];
        __syncthreads();
    }
    if (tid == 0) {
        g_loss_part[blockIdx.x] = red[0];
        __threadfence();
        int old = atomicAdd(&g_done, 1);
        is_last = (old == NBLK - 1);
    }
    __syncthreads();

    // last block to finish reduces the loss scalar (fixed order -> deterministic)
    if (is_last) {
        __threadfence();
        double a = (double)g_loss_part[tid];
        if (tid + 256 < NBLK) a += (double)g_loss_part[tid + 256];
        rd[tid] = a;
        if (tid < EDIM) {
            float v = 0.f;
            #pragma unroll
            for (int j = 0; j < 32; j++) v += g_s_part[j * EDIM + tid];
            sv[tid] = v * v;
        }
        __syncthreads();
        #pragma unroll
        for (int st = 128; st > 0; st >>= 1) {
            if (tid < st) rd[tid] += rd[tid + st];
            __syncthreads();
        }
        if (tid == 0) {
            float c = 0.f;
            for (int j = 0; j < EDIM; j++) c += sv[j];
            out[LOSS_OFF] = (float)(1.25 * (rd[0] / (double)ZLEN))
                          + c / ((float)NE * (float)NE);
        }
    }
}

// ============================================================
extern "C" void kernel_launch(void* const* d_in, const int* in_sizes, int n_in,
                              void* d_out, int out_size) {
    const float* z_    = (const float*)d_in[0];
    const float* convw = (const float*)d_in[1];
    const float* convb = (const float*)d_in[2];
    const float* emb   = (const float*)d_in[3];
    float* out = (float*)d_out;

    cudaFuncSetAttribute(k_argmin, cudaFuncAttributeMaxDynamicSharedMemorySize,
                         SMEM_ARGMIN);

    k_conv<<<256, 128>>>(z_, convw, convb, emb, out);
    k_argmin<<<NBLK, 256, SMEM_ARGMIN>>>(out, emb);
}

// round 12
// speedup vs baseline: 1.0277x; 1.0277x over previous
#include <cuda_runtime.h>
#include <math.h>

// ---------------- problem constants ----------------
#define BATCH   32
#define CIN     256
#define COUT    64
#define HW      1024
#define NE      1024
#define EDIM    64
#define NROWS   32768
#define ZLEN    (BATCH*COUT*HW)   // 2097152
#define TILES   8
#define CODE_TILE 128
#define ROWS_BLK 112              // rows per argmin block (8 warps x 14 rows)
#define RPT      14               // rows per thread (warp-uniform)
#define NBLK     293              // ceil(32768/112); last block 64 valid rows

// output layout (concat, float32): z_q | loss | sampled | min_idx
#define ZQ_OFF   0
#define LOSS_OFF ((size_t)ZLEN)
#define SAMP_OFF ((size_t)ZLEN + 1)
#define MIDX_OFF ((size_t)ZLEN + 1 + NROWS)

// argmin smem: zs4[112*17] | es4[64*33] | Sz[112] | se[128] | red[256]
#define ZS_F4    (ROWS_BLK * 17)          // 1904
#define ES_F4    (64 * 33)                // 2112
#define SMEM_ARGMIN ((ZS_F4 + ES_F4) * 16 + ROWS_BLK * 4 + 128 * 4 + 256 * 4)

// ---------------- device scratch ----------------
__device__ __align__(16) float g_z[ZLEN];
__device__ __align__(16) float g_embi[NE * EDIM];   // pair-interleaved codebook
__device__ int   g_idx[NROWS];
__device__ float g_se[NE];
__device__ float g_loss_part[NBLK];
__device__ float g_s_part[32 * EDIM];
__device__ int   g_done;

// ---------------- packed f32x2 helpers (bit-exact per-lane fma.rn) ----------------
__device__ __forceinline__ unsigned long long dupf(float v) {
    unsigned long long r;
    asm("mov.b64 %0, {%1, %1};" : "=l"(r) : "r"(__float_as_uint(v)));
    return r;
}
__device__ __forceinline__ unsigned long long pack2(float a, float b) {
    unsigned long long r;
    asm("mov.b64 %0, {%1, %2};" : "=l"(r) : "r"(__float_as_uint(a)), "r"(__float_as_uint(b)));
    return r;
}
__device__ __forceinline__ void fma2(unsigned long long& d,
                                     unsigned long long a, unsigned long long b) {
    asm("fma.rn.f32x2 %0, %1, %2, %0;" : "+l"(d) : "l"(a), "l"(b));
}
__device__ __forceinline__ void unpack2(float& lo, float& hi, unsigned long long v) {
    asm("mov.b64 {%0, %1}, %2;" : "=f"(lo), "=f"(hi) : "l"(v));
}

// Replicated XLA-CPU reduce order: VF=4, IC=2, fmla, faddp-adjacent horizontal.
__device__ __forceinline__ float sumsq64_p(const float4* v4) {
    float a0=0.f,a1=0.f,a2=0.f,a3=0.f, b0=0.f,b1=0.f,b2=0.f,b3=0.f;
    #pragma unroll
    for (int t = 0; t < 8; t++) {
        float4 x = v4[2*t];
        a0 = __fmaf_rn(x.x, x.x, a0); a1 = __fmaf_rn(x.y, x.y, a1);
        a2 = __fmaf_rn(x.z, x.z, a2); a3 = __fmaf_rn(x.w, x.w, a3);
        float4 y = v4[2*t+1];
        b0 = __fmaf_rn(y.x, y.x, b0); b1 = __fmaf_rn(y.y, y.y, b1);
        b2 = __fmaf_rn(y.z, y.z, b2); b3 = __fmaf_rn(y.w, y.w, b3);
    }
    float L0 = a0 + b0, L1 = a1 + b1, L2 = a2 + b2, L3 = a3 + b3;
    return (L0 + L1) + (L2 + L3);
}

// ============================================================
// K1: fused prep (codebook interleave) + norms/contrastive + sampled-zero
//     + 1x1 conv (register-tiled, FMA2, bitwise Eigen order).
// Pair layout (128-code tiles): pair-row r = q*32+s (q<2, s<32) holds
// codes (t*128 + 64q + 2s, +1), element-interleaved by k.
// ============================================================
__global__ void __launch_bounds__(128) k_conv(const float* __restrict__ zin,
                                              const float* __restrict__ w,
                                              const float* __restrict__ bias,
                                              const float* __restrict__ emb,
                                              float* __restrict__ out) {
    __shared__ unsigned long long ws[CIN * 8];
    __shared__ float bs[16];
    __shared__ float inv_n[32];
    __shared__ float sq[2][EDIM];

    int tid = threadIdx.x;
    int blk = blockIdx.x;

    // ---- prep: pair-interleave codebook (2 elements per thread) ----
    #pragma unroll
    for (int e = 0; e < 2; e++) {
        int o = blk * 256 + e * 128 + tid;
        int P = o >> 7, r = o & 127;
        int k = r >> 1, l = r & 1;
        int t = P >> 6, rem = P & 63;
        int q = rem >> 5, sl = rem & 31;
        int j = t * 128 + 64 * q + 2 * sl + l;
        g_embi[o] = emb[(size_t)j * EDIM + k];
    }
    // zero 'sampled' region (1:1 thread map) + reset completion counter
    out[SAMP_OFF + blk * 128 + tid] = 0.0f;
    if (blk == 0 && tid == 0) g_done = 0;

    // ---- norms + contrastive partials (blocks 0..31) ----
    if (blk < 32) {
        if (tid < 32) {
            int i = blk * 32 + tid;
            float v = sumsq64_p((const float4*)(emb + (size_t)i * EDIM));
            g_se[i] = v;
            inv_n[tid] = 1.0f / sqrtf(v);
        }
        __syncthreads();
        int k = tid & 63, q = tid >> 6;
        float sacc = 0.f;
        #pragma unroll
        for (int i = 0; i < 16; i++) {
            int code = q * 16 + i;
            sacc += emb[(size_t)(blk * 32 + code) * EDIM + k] * inv_n[code];
        }
        sq[q][k] = sacc;
        __syncthreads();
        if (tid < EDIM)
            g_s_part[blk * EDIM + tid] = sq[0][tid] + sq[1][tid];
    }
    __syncthreads();

    // ---- conv ----
    int b = blk >> 3, half = (blk >> 2) & 1, og = blk & 3;
    int obase = og * 16;

    for (int m = tid; m < CIN * 8; m += 128) {
        int c = m >> 3, u = m & 7;
        const float* wp = w + (size_t)(obase + 2 * u) * CIN + c;
        ws[m] = pack2(wp[0], wp[CIN]);
    }
    if (tid < 16) bs[tid] = bias[obase + tid];
    __syncthreads();

    int p0 = half * 512 + tid;
    const float* zp = zin + (size_t)b * CIN * HW + p0;

    unsigned long long acc[8][4];
    #pragma unroll
    for (int u = 0; u < 8; u++)
        #pragma unroll
        for (int j = 0; j < 4; j++) acc[u][j] = 0ULL;

    float zn[4][8];
    #pragma unroll
    for (int j = 0; j < 4; j++)
        #pragma unroll
        for (int i = 0; i < 8; i++)
            zn[j][i] = zp[(size_t)i * HW + 128 * j];

    const ulonglong2* ws2 = (const ulonglong2*)ws;
    for (int ch = 0; ch < 32; ch++) {
        float zc[4][8];
        #pragma unroll
        for (int j = 0; j < 4; j++)
            #pragma unroll
            for (int i = 0; i < 8; i++) zc[j][i] = zn[j][i];
        if (ch < 31) {
            #pragma unroll
            for (int j = 0; j < 4; j++)
                #pragma unroll
                for (int i = 0; i < 8; i++)
                    zn[j][i] = zp[(size_t)((ch + 1) * 8 + i) * HW + 128 * j];
        }
        #pragma unroll
        for (int cc = 0; cc < 8; cc++) {
            int c = ch * 8 + cc;
            unsigned long long zz[4];
            #pragma unroll
            for (int j = 0; j < 4; j++) zz[j] = dupf(zc[j][cc]);
            const ulonglong2* wrow = ws2 + c * 4;
            #pragma unroll
            for (int uu = 0; uu < 4; uu++) {
                ulonglong2 wp = wrow[uu];
                #pragma unroll
                for (int j = 0; j < 4; j++) {
                    fma2(acc[2*uu][j],     zz[j], wp.x);
                    fma2(acc[2*uu + 1][j], zz[j], wp.y);
                }
            }
        }
    }

    float* zo = g_z + (size_t)b * COUT * HW;
    #pragma unroll
    for (int u = 0; u < 8; u++) {
        int o = obase + 2 * u;
        #pragma unroll
        for (int j = 0; j < 4; j++) {
            float lo, hi;
            unpack2(lo, hi, acc[u][j]);
            zo[(size_t)o * HW + p0 + 128 * j]       = lo + bs[2*u];
            zo[(size_t)(o + 1) * HW + p0 + 128 * j] = hi + bs[2*u + 1];
        }
    }
}

// ============================================================
// K2: fused distance+argmin + scatter + loss (last-block finalize).
// Warp = 32 distinct code-sublanes x 1 row-group: e-LDS fully distinct
// (no duplication), z broadcast. 14 rows x 2 pairs per thread,
// 112 rows/block, grid 293, occ 2.
// d_j = fl( fl(Sz+Se_j) - 2*dot_j ), dot = in-order 64-term FMA chain.
// ============================================================
__global__ void __launch_bounds__(256, 2) k_argmin(float* __restrict__ out,
                                                   const float* __restrict__ emb) {
    extern __shared__ __align__(16) char smem[];
    float4* zs4  = (float4*)smem;                  // [112][17]
    float4* es4  = zs4 + ZS_F4;                    // [64 pair-rows][33]
    float*  Sz_s = (float*)(es4 + ES_F4);          // [112]
    float*  se_s = Sz_s + ROWS_BLK;                // [128]
    float*  red  = se_s + 128;                     // [256]
    __shared__ int    is_last;
    __shared__ double rd[256];
    __shared__ float  sv[EDIM];

    int tid = threadIdx.x;
    int s   = tid & 31;                            // code sublane 0..31
    int g   = tid >> 5;                            // warp = row group 0..7
    int row0 = blockIdx.x * ROWS_BLK;

    // stage z rows (clamped for last block): 1792 float4
    {
        const float4* zall = (const float4*)g_z;
        #pragma unroll
        for (int j = 0; j < 7; j++) {
            int idx = tid + 256 * j;               // 0..1791
            int r = idx >> 4, k4 = idx & 15;
            int grow = row0 + r;
            if (grow > NROWS - 1) grow = NROWS - 1;
            zs4[r * 17 + k4] = zall[(size_t)grow * 16 + k4];
        }
    }
    __syncthreads();
    if (tid < ROWS_BLK)
        Sz_s[tid] = sumsq64_p(zs4 + tid * 17);

    float best[RPT];
    int   bi[RPT];
    #pragma unroll
    for (int i = 0; i < RPT; i++) { best[i] = 3.4e38f; bi[i] = 0; }

    const float4* gsrc = (const float4*)g_embi;
    const ulonglong2* eb0 = ((const ulonglong2*)es4) + s * 33;          // q=0
    const ulonglong2* eb1 = ((const ulonglong2*)es4) + (32 + s) * 33;   // q=1

    for (int t = 0; t < TILES; t++) {
        __syncthreads();      // prior tile's reads complete (and Sz on t=0)
        {
            const float4* src = gsrc + (size_t)t * 2048;
            #pragma unroll
            for (int j = 0; j < 8; j++) {
                int idx = tid + 256 * j;
                int pr = idx >> 5, wv = idx & 31;
                es4[pr * 33 + wv] = src[idx];
            }
            if (tid < CODE_TILE) se_s[tid] = g_se[t * CODE_TILE + tid];
        }
        __syncthreads();

        unsigned long long acc[RPT][2];
        #pragma unroll
        for (int i = 0; i < RPT; i++) { acc[i][0] = 0ULL; acc[i][1] = 0ULL; }

        #pragma unroll 4
        for (int k4 = 0; k4 < 16; k4++) {
            // e: 4 LDS.128, all 512B distinct across the 32 sublanes
            ulonglong2 e0A = eb0[2 * k4];       // q=0, dims 4k4,4k4+1
            ulonglong2 e0B = eb0[2 * k4 + 1];   // q=0, dims 4k4+2,4k4+3
            ulonglong2 e1A = eb1[2 * k4];       // q=1
            ulonglong2 e1B = eb1[2 * k4 + 1];
            #pragma unroll
            for (int i = 0; i < RPT; i++) {
                float4 z = zs4[(g + 8 * i) * 17 + k4];   // broadcast
                unsigned long long zx = dupf(z.x), zy = dupf(z.y),
                                   zz = dupf(z.z), zw = dupf(z.w);
                fma2(acc[i][0], zx, e0A.x); fma2(acc[i][0], zy, e0A.y);
                fma2(acc[i][0], zz, e0B.x); fma2(acc[i][0], zw, e0B.y);
                fma2(acc[i][1], zx, e1A.x); fma2(acc[i][1], zy, e1A.y);
                fma2(acc[i][1], zz, e1B.x); fma2(acc[i][1], zw, e1B.y);
            }
        }

        // eval: per thread q ascending -> codes 2s+64q, 2s+64q+1 ascending
        #pragma unroll
        for (int q = 0; q < 2; q++) {
            int jlo = 2 * s + 64 * q, jhi = jlo + 1;
            float selo = se_s[jlo], sehi = se_s[jhi];
            #pragma unroll
            for (int i = 0; i < RPT; i++) {
                float Szv = Sz_s[g + 8 * i];             // broadcast
                float dlo, dhi;
                unpack2(dlo, dhi, acc[i][q]);
                float dv = __fmaf_rn(-2.0f, dlo, Szv + selo);
                if (dv < best[i]) { best[i] = dv; bi[i] = t * CODE_TILE + jlo; }
                float dw = __fmaf_rn(-2.0f, dhi, Szv + sehi);
                if (dw < best[i]) { best[i] = dw; bi[i] = t * CODE_TILE + jhi; }
            }
        }
    }

    // lexicographic merge across the full 32-lane warp (per row)
    unsigned m = 0xffffffffu;
    #pragma unroll
    for (int i = 0; i < RPT; i++) {
        float bv = best[i]; int bj = bi[i];
        #pragma unroll
        for (int off = 16; off > 0; off >>= 1) {
            float ob = __shfl_down_sync(m, bv, off);
            int   oi = __shfl_down_sync(m, bj, off);
            if (ob < bv || (ob == bv && oi < bj)) { bv = ob; bj = oi; }
        }
        bj = __shfl_sync(m, bj, 0);
        bi[i] = bj;
    }

    // epilogue: lanes 0-15 handle row ii, lanes 16-31 row ii+7 (const idx)
    float lacc = 0.f;
    int c = s & 15;   // float4 column
    #pragma unroll
    for (int ii = 0; ii < 7; ii++) {
        if (s < 16) {
            int rl = g + 8 * ii;
            int row = row0 + rl;
            if (row < NROWS) {
                int bj = bi[ii];
                if (c == 0) {
                    g_idx[row] = bj;
                    out[MIDX_OFF + row] = (float)bj;
                    out[SAMP_OFF + bj] = 1.0f;
                }
                float4 e = ((const float4*)(emb + (size_t)bj * EDIM))[c];
                float4 z = zs4[rl * 17 + c];
                float dx = e.x - z.x, dy = e.y - z.y, dz = e.z - z.z, dw = e.w - z.w;
                float4 o;
                o.x = z.x + dx; o.y = z.y + dy; o.z = z.z + dz; o.w = z.w + dw;
                ((float4*)(out + ZQ_OFF + (size_t)row * EDIM))[c] = o;
                lacc += dx*dx + dy*dy + dz*dz + dw*dw;
            }
        } else {
            int rl = g + 8 * (ii + 7);
            int row = row0 + rl;
            if (row < NROWS) {
                int bj = bi[ii + 7];
                if (c == 0) {
                    g_idx[row] = bj;
                    out[MIDX_OFF + row] = (float)bj;
                    out[SAMP_OFF + bj] = 1.0f;
                }
                float4 e = ((const float4*)(emb + (size_t)bj * EDIM))[c];
                float4 z = zs4[rl * 17 + c];
                float dx = e.x - z.x, dy = e.y - z.y, dz = e.z - z.z, dw = e.w - z.w;
                float4 o;
                o.x = z.x + dx; o.y = z.y + dy; o.z = z.z + dz; o.w = z.w + dw;
                ((float4*)(out + ZQ_OFF + (size_t)row * EDIM))[c] = o;
                lacc += dx*dx + dy*dy + dz*dz + dw*dw;
            }
        }
    }
    red[tid] = lacc;
    __syncthreads();
    #pragma unroll
    for (int st = 128; st > 0; st >>= 1) {
        if (tid < st) red[tid] += red[tid + st];
        __syncthreads();
    }
    if (tid == 0) {
        g_loss_part[blockIdx.x] = red[0];
        __threadfence();
        int old = atomicAdd(&g_done, 1);
        is_last = (old == NBLK - 1);
    }
    __syncthreads();

    // last block to finish reduces the loss scalar (fixed order -> deterministic)
    if (is_last) {
        __threadfence();
        double a = (double)g_loss_part[tid];
        if (tid + 256 < NBLK) a += (double)g_loss_part[tid + 256];
        rd[tid] = a;
        if (tid < EDIM) {
            float v = 0.f;
            #pragma unroll
            for (int j = 0; j < 32; j++) v += g_s_part[j * EDIM + tid];
            sv[tid] = v * v;
        }
        __syncthreads();
        #pragma unroll
        for (int st = 128; st > 0; st >>= 1) {
            if (tid < st) rd[tid] += rd[tid + st];
            __syncthreads();
        }
        if (tid == 0) {
            float cc = 0.f;
            for (int j = 0; j < EDIM; j++) cc += sv[j];
            out[LOSS_OFF] = (float)(1.25 * (rd[0] / (double)ZLEN))
                          + cc / ((float)NE * (float)NE);
        }
    }
}

// ============================================================
extern "C" void kernel_launch(void* const* d_in, const int* in_sizes, int n_in,
                              void* d_out, int out_size) {
    const float* z_    = (const float*)d_in[0];
    const float* convw = (const float*)d_in[1];
    const float* convb = (const float*)d_in[2];
    const float* emb   = (const float*)d_in[3];
    float* out = (float*)d_out;

    cudaFuncSetAttribute(k_argmin, cudaFuncAttributeMaxDynamicSharedMemorySize,
                         SMEM_ARGMIN);

    k_conv<<<256, 128>>>(z_, convw, convb, emb, out);
    k_argmin<<<NBLK, 256, SMEM_ARGMIN>>>(out, emb);
}

// round 13
// speedup vs baseline: 1.1653x; 1.1339x over previous
#include <cuda_runtime.h>
#include <math.h>

// ---------------- problem constants ----------------
#define BATCH   32
#define CIN     256
#define COUT    64
#define HW      1024
#define NE      1024
#define EDIM    64
#define NROWS   32768
#define ZLEN    (BATCH*COUT*HW)   // 2097152
#define TILES   8
#define CODE_TILE 128
#define ROWS_BLK 112              // rows per argmin block (16 groups x RPT)
#define RPT      7                // rows per thread
#define NBLK     293              // ceil(32768/112)

// output layout (concat, float32): z_q | loss | sampled | min_idx
#define ZQ_OFF   0
#define LOSS_OFF ((size_t)ZLEN)
#define SAMP_OFF ((size_t)ZLEN + 1)
#define MIDX_OFF ((size_t)ZLEN + 1 + NROWS)

// argmin smem: zs4[112*17] | es4[2][64*33] | Sz[112] | se[2][128] | red[256]
#define ZS_F4    (ROWS_BLK * 17)          // 1904
#define ES_F4    (64 * 33)                // 2112 per buffer
#define SMEM_ARGMIN ((ZS_F4 + 2*ES_F4) * 16 + ROWS_BLK * 4 + 256 * 4 + 256 * 4)

// ---------------- device scratch ----------------
__device__ __align__(16) float g_z[ZLEN];
__device__ __align__(16) float g_embi[NE * EDIM];   // pair-interleaved codebook
__device__ int   g_idx[NROWS];
__device__ float g_se[NE];
__device__ float g_loss_part[NBLK];
__device__ float g_s_part[32 * EDIM];
__device__ int   g_done;

// ---------------- packed f32x2 helpers (bit-exact per-lane fma.rn) ----------------
__device__ __forceinline__ unsigned long long dupf(float v) {
    unsigned long long r;
    asm("mov.b64 %0, {%1, %1};" : "=l"(r) : "r"(__float_as_uint(v)));
    return r;
}
__device__ __forceinline__ unsigned long long pack2(float a, float b) {
    unsigned long long r;
    asm("mov.b64 %0, {%1, %2};" : "=l"(r) : "r"(__float_as_uint(a)), "r"(__float_as_uint(b)));
    return r;
}
__device__ __forceinline__ void fma2(unsigned long long& d,
                                     unsigned long long a, unsigned long long b) {
    asm("fma.rn.f32x2 %0, %1, %2, %0;" : "+l"(d) : "l"(a), "l"(b));
}
__device__ __forceinline__ void unpack2(float& lo, float& hi, unsigned long long v) {
    asm("mov.b64 {%0, %1}, %2;" : "=f"(lo), "=f"(hi) : "l"(v));
}

// Replicated XLA-CPU reduce order: VF=4, IC=2, fmla, faddp-adjacent horizontal.
__device__ __forceinline__ float sumsq64_p(const float4* v4) {
    float a0=0.f,a1=0.f,a2=0.f,a3=0.f, b0=0.f,b1=0.f,b2=0.f,b3=0.f;
    #pragma unroll
    for (int t = 0; t < 8; t++) {
        float4 x = v4[2*t];
        a0 = __fmaf_rn(x.x, x.x, a0); a1 = __fmaf_rn(x.y, x.y, a1);
        a2 = __fmaf_rn(x.z, x.z, a2); a3 = __fmaf_rn(x.w, x.w, a3);
        float4 y = v4[2*t+1];
        b0 = __fmaf_rn(y.x, y.x, b0); b1 = __fmaf_rn(y.y, y.y, b1);
        b2 = __fmaf_rn(y.z, y.z, b2); b3 = __fmaf_rn(y.w, y.w, b3);
    }
    float L0 = a0 + b0, L1 = a1 + b1, L2 = a2 + b2, L3 = a3 + b3;
    return (L0 + L1) + (L2 + L3);
}

// ============================================================
// K1: fused prep (codebook interleave) + norms/contrastive + sampled-zero
//     + 1x1 conv (register-tiled, FMA2, bitwise Eigen order).
// 512 blocks x 128 threads: 2 px x 16 outputs per thread (better
// warp residency than 4-px version; same FMA2 count and chains).
// Pair layout (128-code tiles): pair-row r = q*16+s holds codes
// (t*128 + 8s + 2q, +1), element-interleaved by k.
// ============================================================
__global__ void __launch_bounds__(128) k_conv(const float* __restrict__ zin,
                                              const float* __restrict__ w,
                                              const float* __restrict__ bias,
                                              const float* __restrict__ emb,
                                              float* __restrict__ out) {
    __shared__ unsigned long long ws[CIN * 8];
    __shared__ float bs[16];
    __shared__ float inv_n[32];
    __shared__ float sq[2][EDIM];

    int tid = threadIdx.x;
    int blk = blockIdx.x;

    // ---- prep: pair-interleave codebook (1 element per thread) ----
    {
        int o = blk * 128 + tid;                  // 0..65535
        int P = o >> 7, r = o & 127;
        int k = r >> 1, l = r & 1;
        int t = P >> 6, rem = P & 63;
        int q = rem >> 4, sl = rem & 15;
        int j = t * 128 + 8 * sl + 2 * q + l;
        g_embi[o] = emb[(size_t)j * EDIM + k];
    }
    // zero 'sampled' region + reset completion counter
    if (blk < 256) out[SAMP_OFF + blk * 128 + tid] = 0.0f;
    if (blk == 0 && tid == 0) g_done = 0;

    // ---- norms + contrastive partials (blocks 0..31) ----
    if (blk < 32) {
        if (tid < 32) {
            int i = blk * 32 + tid;
            float v = sumsq64_p((const float4*)(emb + (size_t)i * EDIM));
            g_se[i] = v;
            inv_n[tid] = 1.0f / sqrtf(v);
        }
        __syncthreads();
        int k = tid & 63, q = tid >> 6;
        float sacc = 0.f;
        #pragma unroll
        for (int i = 0; i < 16; i++) {
            int code = q * 16 + i;
            sacc += emb[(size_t)(blk * 32 + code) * EDIM + k] * inv_n[code];
        }
        sq[q][k] = sacc;
        __syncthreads();
        if (tid < EDIM)
            g_s_part[blk * EDIM + tid] = sq[0][tid] + sq[1][tid];
    }
    __syncthreads();

    // ---- conv: blk -> (b, quarter, og); thread -> pixels p0, p0+128 ----
    int b = blk >> 4;
    int quarter = (blk >> 2) & 3, og = blk & 3;
    int obase = og * 16;

    for (int m = tid; m < CIN * 8; m += 128) {
        int c = m >> 3, u = m & 7;
        const float* wp = w + (size_t)(obase + 2 * u) * CIN + c;
        ws[m] = pack2(wp[0], wp[CIN]);
    }
    if (tid < 16) bs[tid] = bias[obase + tid];
    __syncthreads();

    int p0 = quarter * 256 + tid;
    const float* zp = zin + (size_t)b * CIN * HW + p0;

    unsigned long long acc[8][2];
    #pragma unroll
    for (int u = 0; u < 8; u++) { acc[u][0] = 0ULL; acc[u][1] = 0ULL; }

    float zn[2][8];
    #pragma unroll
    for (int j = 0; j < 2; j++)
        #pragma unroll
        for (int i = 0; i < 8; i++)
            zn[j][i] = zp[(size_t)i * HW + 128 * j];

    const ulonglong2* ws2 = (const ulonglong2*)ws;
    for (int ch = 0; ch < 32; ch++) {
        float zc[2][8];
        #pragma unroll
        for (int j = 0; j < 2; j++)
            #pragma unroll
            for (int i = 0; i < 8; i++) zc[j][i] = zn[j][i];
        if (ch < 31) {
            #pragma unroll
            for (int j = 0; j < 2; j++)
                #pragma unroll
                for (int i = 0; i < 8; i++)
                    zn[j][i] = zp[(size_t)((ch + 1) * 8 + i) * HW + 128 * j];
        }
        #pragma unroll
        for (int cc = 0; cc < 8; cc++) {
            int c = ch * 8 + cc;
            unsigned long long zz0 = dupf(zc[0][cc]);
            unsigned long long zz1 = dupf(zc[1][cc]);
            const ulonglong2* wrow = ws2 + c * 4;
            #pragma unroll
            for (int uu = 0; uu < 4; uu++) {
                ulonglong2 wp = wrow[uu];
                fma2(acc[2*uu][0],     zz0, wp.x);
                fma2(acc[2*uu][1],     zz1, wp.x);
                fma2(acc[2*uu + 1][0], zz0, wp.y);
                fma2(acc[2*uu + 1][1], zz1, wp.y);
            }
        }
    }

    float* zo = g_z + (size_t)b * COUT * HW;
    #pragma unroll
    for (int u = 0; u < 8; u++) {
        int o = obase + 2 * u;
        #pragma unroll
        for (int j = 0; j < 2; j++) {
            float lo, hi;
            unpack2(lo, hi, acc[u][j]);
            zo[(size_t)o * HW + p0 + 128 * j]       = lo + bs[2*u];
            zo[(size_t)(o + 1) * HW + p0 + 128 * j] = hi + bs[2*u + 1];
        }
    }
}

// ============================================================
// K2: fused distance+argmin + scatter + loss (last-block finalize).
// 7 rows x 4 code-pairs per thread, 112 rows/block, grid 293,
// double-buffered e tiles (proven R9 config, 97.8us).
// d_j = fl( fl(Sz+Se_j) - 2*dot_j ), dot = in-order 64-term FMA chain.
// ============================================================
__global__ void __launch_bounds__(256, 2) k_argmin(float* __restrict__ out,
                                                   const float* __restrict__ emb) {
    extern __shared__ __align__(16) char smem[];
    float4* zs4  = (float4*)smem;                  // [112][17]
    float4* es4  = zs4 + ZS_F4;                    // [2][64 pair-rows][33]
    float*  Sz_s = (float*)(es4 + 2 * ES_F4);      // [112]
    float*  se_s = Sz_s + ROWS_BLK;                // [2][128]
    float*  red  = se_s + 256;                     // [256]
    __shared__ int    is_last;
    __shared__ double rd[256];
    __shared__ float  sv[EDIM];

    int tid = threadIdx.x;
    int s   = tid & 15;                            // code sublane 0..15
    int g   = tid >> 4;                            // row group 0..15
    int row0 = blockIdx.x * ROWS_BLK;

    // stage z rows (clamped for last block) + e tile 0 + se tile 0
    {
        const float4* zall = (const float4*)g_z;
        #pragma unroll
        for (int j = 0; j < RPT; j++) {
            int idx = tid + 256 * j;
            int r = idx >> 4, k4 = idx & 15;
            int grow = row0 + r;
            if (grow > NROWS - 1) grow = NROWS - 1;
            zs4[r * 17 + k4] = zall[(size_t)grow * 16 + k4];
        }
        const float4* src = (const float4*)g_embi;
        #pragma unroll
        for (int j = 0; j < 8; j++) {
            int idx = tid + 256 * j;
            int pr = idx >> 5, wv = idx & 31;
            es4[pr * 33 + wv] = src[idx];
        }
        if (tid < CODE_TILE) se_s[tid] = g_se[tid];
    }
    __syncthreads();
    if (tid < ROWS_BLK)
        Sz_s[tid] = sumsq64_p(zs4 + tid * 17);
    __syncthreads();

    float best[RPT];
    int   bi[RPT];
    #pragma unroll
    for (int i = 0; i < RPT; i++) { best[i] = 3.4e38f; bi[i] = 0; }

    const float4* gsrc = (const float4*)g_embi;
    const float2* zb = ((const float2*)zs4) + g * 34;

    for (int t = 0; t < TILES; t++) {
        int cur = t & 1, nxt = 1 - cur;

        if (t + 1 < TILES) {
            const float4* src = gsrc + (size_t)(t + 1) * 2048;
            #pragma unroll
            for (int j = 0; j < 8; j++) {
                int idx = tid + 256 * j;
                int pr = idx >> 5, wv = idx & 31;
                es4[nxt * ES_F4 + pr * 33 + wv] = src[idx];
            }
            if (tid < CODE_TILE)
                se_s[nxt * 128 + tid] = g_se[(t + 1) * CODE_TILE + tid];
        }

        unsigned long long acc[RPT][4];
        #pragma unroll
        for (int i = 0; i < RPT; i++)
            #pragma unroll
            for (int q = 0; q < 4; q++) acc[i][q] = 0ULL;

        const ulonglong2* ebase = ((const ulonglong2*)(es4 + cur * ES_F4)) + s * 33;

        #pragma unroll 4
        for (int k4 = 0; k4 < 16; k4++) {
            unsigned long long zx[RPT], zy[RPT];
            // half A: dims 4k4, 4k4+1
            #pragma unroll
            for (int i = 0; i < RPT; i++) {
                float2 h = zb[544 * i + 2 * k4];
                zx[i] = dupf(h.x); zy[i] = dupf(h.y);
            }
            #pragma unroll
            for (int q = 0; q < 4; q++) {
                ulonglong2 e01 = ebase[q * 528 + 2 * k4];
                #pragma unroll
                for (int i = 0; i < RPT; i++) {
                    fma2(acc[i][q], zx[i], e01.x);
                    fma2(acc[i][q], zy[i], e01.y);
                }
            }
            // half B: dims 4k4+2, 4k4+3
            #pragma unroll
            for (int i = 0; i < RPT; i++) {
                float2 h = zb[544 * i + 2 * k4 + 1];
                zx[i] = dupf(h.x); zy[i] = dupf(h.y);
            }
            #pragma unroll
            for (int q = 0; q < 4; q++) {
                ulonglong2 e23 = ebase[q * 528 + 2 * k4 + 1];
                #pragma unroll
                for (int i = 0; i < RPT; i++) {
                    fma2(acc[i][q], zx[i], e23.x);
                    fma2(acc[i][q], zy[i], e23.y);
                }
            }
        }

        // eval: per row, q ascending -> codes 8s+2q, 8s+2q+1 ascending
        #pragma unroll
        for (int q = 0; q < 4; q++) {
            int jlo = 8 * s + 2 * q, jhi = jlo + 1;
            float selo = se_s[cur * 128 + jlo], sehi = se_s[cur * 128 + jhi];
            #pragma unroll
            for (int i = 0; i < RPT; i++) {
                float Szv = Sz_s[g + 16 * i];
                float dlo, dhi;
                unpack2(dlo, dhi, acc[i][q]);
                float dv = __fmaf_rn(-2.0f, dlo, Szv + selo);
                if (dv < best[i]) { best[i] = dv; bi[i] = t * CODE_TILE + jlo; }
                float dw = __fmaf_rn(-2.0f, dhi, Szv + sehi);
                if (dw < best[i]) { best[i] = dw; bi[i] = t * CODE_TILE + jhi; }
            }
        }
        __syncthreads();
    }

    // lexicographic merge across the 16 sublanes (per row)
    unsigned m = 0xffffffffu;
    #pragma unroll
    for (int i = 0; i < RPT; i++) {
        float bv = best[i]; int bj = bi[i];
        #pragma unroll
        for (int off = 8; off > 0; off >>= 1) {
            float ob = __shfl_down_sync(m, bv, off, 16);
            int   oi = __shfl_down_sync(m, bj, off, 16);
            if (ob < bv || (ob == bv && oi < bj)) { bv = ob; bj = oi; }
        }
        bj = __shfl_sync(m, bj, 0, 16);
        bi[i] = bj;
    }

    // epilogue per valid row: idx/min_idx/scatter, z_q_st, loss partial
    float lacc = 0.f;
    #pragma unroll
    for (int i = 0; i < RPT; i++) {
        int rl = g + 16 * i;
        int row = row0 + rl;
        if (row < NROWS) {
            int bj = bi[i];
            if (s == 0) {
                g_idx[row] = bj;
                out[MIDX_OFF + row] = (float)bj;
                out[SAMP_OFF + bj] = 1.0f;   // sampled scatter (zeroed by k_conv)
            }
            float4 e = ((const float4*)(emb + (size_t)bj * EDIM))[s];
            float4 z = zs4[rl * 17 + s];
            float dx = e.x - z.x, dy = e.y - z.y, dz = e.z - z.z, dw = e.w - z.w;
            float4 o;
            o.x = z.x + dx; o.y = z.y + dy; o.z = z.z + dz; o.w = z.w + dw;
            ((float4*)(out + ZQ_OFF + (size_t)row * EDIM))[s] = o;
            lacc += dx*dx + dy*dy + dz*dz + dw*dw;
        }
    }
    red[tid] = lacc;
    __syncthreads();
    #pragma unroll
    for (int st = 128; st > 0; st >>= 1) {
        if (tid < st) red[tid] += red[tid + st];
        __syncthreads();
    }
    if (tid == 0) {
        g_loss_part[blockIdx.x] = red[0];
        __threadfence();
        int old = atomicAdd(&g_done, 1);
        is_last = (old == NBLK - 1);
    }
    __syncthreads();

    // last block to finish reduces the loss scalar (fixed order -> deterministic)
    if (is_last) {
        __threadfence();
        double a = (double)g_loss_part[tid];
        if (tid + 256 < NBLK) a += (double)g_loss_part[tid + 256];
        rd[tid] = a;
        if (tid < EDIM) {
            float v = 0.f;
            #pragma unroll
            for (int j = 0; j < 32; j++) v += g_s_part[j * EDIM + tid];
            sv[tid] = v * v;
        }
        __syncthreads();
        #pragma unroll
        for (int st = 128; st > 0; st >>= 1) {
            if (tid < st) rd[tid] += rd[tid + st];
            __syncthreads();
        }
        if (tid == 0) {
            float c = 0.f;
            for (int j = 0; j < EDIM; j++) c += sv[j];
            out[LOSS_OFF] = (float)(1.25 * (rd[0] / (double)ZLEN))
                          + c / ((float)NE * (float)NE);
        }
    }
}

// ============================================================
extern "C" void kernel_launch(void* const* d_in, const int* in_sizes, int n_in,
                              void* d_out, int out_size) {
    const float* z_    = (const float*)d_in[0];
    const float* convw = (const float*)d_in[1];
    const float* convb = (const float*)d_in[2];
    const float* emb   = (const float*)d_in[3];
    float* out = (float*)d_out;

    cudaFuncSetAttribute(k_argmin, cudaFuncAttributeMaxDynamicSharedMemorySize,
                         SMEM_ARGMIN);

    k_conv<<<512, 128>>>(z_, convw, convb, emb, out);
    k_argmin<<<NBLK, 256, SMEM_ARGMIN>>>(out, emb);
}

// round 14
// speedup vs baseline: 1.1777x; 1.0107x over previous
#include <cuda_runtime.h>
#include <math.h>

// ---------------- problem constants ----------------
#define BATCH   32
#define CIN     256
#define COUT    64
#define HW      1024
#define NE      1024
#define EDIM    64
#define NROWS   32768
#define ZLEN    (BATCH*COUT*HW)   // 2097152
#define TILES   8
#define CODE_TILE 128
#define ROWS_BLK 112              // rows per argmin block (16 groups x RPT)
#define RPT      7                // rows per thread
#define NBLK     293              // ceil(32768/112)

// output layout (concat, float32): z_q | loss | sampled | min_idx
#define ZQ_OFF   0
#define LOSS_OFF ((size_t)ZLEN)
#define SAMP_OFF ((size_t)ZLEN + 1)
#define MIDX_OFF ((size_t)ZLEN + 1 + NROWS)

// argmin smem: zs4[112*17] | es4[2][64*33] | Sz[112] | se[2][128] | red[256]
#define ZS_F4    (ROWS_BLK * 17)          // 1904
#define ES_F4    (64 * 33)                // 2112 per buffer
#define SMEM_ARGMIN ((ZS_F4 + 2*ES_F4) * 16 + ROWS_BLK * 4 + 256 * 4 + 256 * 4)

// ---------------- device scratch ----------------
__device__ __align__(16) float g_z[ZLEN];
__device__ __align__(16) float g_embi[NE * EDIM];   // pair-interleaved codebook
__device__ int   g_idx[NROWS];
__device__ float g_se[NE];
__device__ float g_loss_part[NBLK];
__device__ float g_s_part[32 * EDIM];
__device__ int   g_done;

// ---------------- packed f32x2 helpers (bit-exact per-lane ops) ----------------
__device__ __forceinline__ unsigned long long dupf(float v) {
    unsigned long long r;
    asm("mov.b64 %0, {%1, %1};" : "=l"(r) : "r"(__float_as_uint(v)));
    return r;
}
__device__ __forceinline__ unsigned long long pack2(float a, float b) {
    unsigned long long r;
    asm("mov.b64 %0, {%1, %2};" : "=l"(r) : "r"(__float_as_uint(a)), "r"(__float_as_uint(b)));
    return r;
}
__device__ __forceinline__ void fma2(unsigned long long& d,
                                     unsigned long long a, unsigned long long b) {
    asm("fma.rn.f32x2 %0, %1, %2, %0;" : "+l"(d) : "l"(a), "l"(b));
}
__device__ __forceinline__ unsigned long long add2(unsigned long long a,
                                                   unsigned long long b) {
    unsigned long long d;
    asm("add.rn.f32x2 %0, %1, %2;" : "=l"(d) : "l"(a), "l"(b));
    return d;
}
__device__ __forceinline__ void unpack2(float& lo, float& hi, unsigned long long v) {
    asm("mov.b64 {%0, %1}, %2;" : "=f"(lo), "=f"(hi) : "l"(v));
}

// Replicated XLA-CPU reduce order: VF=4, IC=2, fmla, faddp-adjacent horizontal.
__device__ __forceinline__ float sumsq64_p(const float4* v4) {
    float a0=0.f,a1=0.f,a2=0.f,a3=0.f, b0=0.f,b1=0.f,b2=0.f,b3=0.f;
    #pragma unroll
    for (int t = 0; t < 8; t++) {
        float4 x = v4[2*t];
        a0 = __fmaf_rn(x.x, x.x, a0); a1 = __fmaf_rn(x.y, x.y, a1);
        a2 = __fmaf_rn(x.z, x.z, a2); a3 = __fmaf_rn(x.w, x.w, a3);
        float4 y = v4[2*t+1];
        b0 = __fmaf_rn(y.x, y.x, b0); b1 = __fmaf_rn(y.y, y.y, b1);
        b2 = __fmaf_rn(y.z, y.z, b2); b3 = __fmaf_rn(y.w, y.w, b3);
    }
    float L0 = a0 + b0, L1 = a1 + b1, L2 = a2 + b2, L3 = a3 + b3;
    return (L0 + L1) + (L2 + L3);
}

// ============================================================
// K1: fused prep (codebook interleave) + norms/contrastive + sampled-zero
//     + 1x1 conv (register-tiled, FMA2, bitwise Eigen order).
// 512 blocks x 128 threads: 2 px x 16 outputs per thread.
// Pair layout (128-code tiles): pair-row r = q*16+s holds codes
// (t*128 + 8s + 2q, +1), element-interleaved by k.
// ============================================================
__global__ void __launch_bounds__(128) k_conv(const float* __restrict__ zin,
                                              const float* __restrict__ w,
                                              const float* __restrict__ bias,
                                              const float* __restrict__ emb,
                                              float* __restrict__ out) {
    __shared__ unsigned long long ws[CIN * 8];
    __shared__ float bs[16];
    __shared__ float inv_n[32];
    __shared__ float sq[2][EDIM];

    int tid = threadIdx.x;
    int blk = blockIdx.x;

    // ---- prep: pair-interleave codebook (1 element per thread) ----
    {
        int o = blk * 128 + tid;                  // 0..65535
        int P = o >> 7, r = o & 127;
        int k = r >> 1, l = r & 1;
        int t = P >> 6, rem = P & 63;
        int q = rem >> 4, sl = rem & 15;
        int j = t * 128 + 8 * sl + 2 * q + l;
        g_embi[o] = emb[(size_t)j * EDIM + k];
    }
    // zero 'sampled' region + reset completion counter
    if (blk < 256) out[SAMP_OFF + blk * 128 + tid] = 0.0f;
    if (blk == 0 && tid == 0) g_done = 0;

    // ---- norms + contrastive partials (blocks 0..31) ----
    if (blk < 32) {
        if (tid < 32) {
            int i = blk * 32 + tid;
            float v = sumsq64_p((const float4*)(emb + (size_t)i * EDIM));
            g_se[i] = v;
            inv_n[tid] = 1.0f / sqrtf(v);
        }
        __syncthreads();
        int k = tid & 63, q = tid >> 6;
        float sacc = 0.f;
        #pragma unroll
        for (int i = 0; i < 16; i++) {
            int code = q * 16 + i;
            sacc += emb[(size_t)(blk * 32 + code) * EDIM + k] * inv_n[code];
        }
        sq[q][k] = sacc;
        __syncthreads();
        if (tid < EDIM)
            g_s_part[blk * EDIM + tid] = sq[0][tid] + sq[1][tid];
    }
    __syncthreads();

    // ---- conv: blk -> (b, quarter, og); thread -> pixels p0, p0+128 ----
    int b = blk >> 4;
    int quarter = (blk >> 2) & 3, og = blk & 3;
    int obase = og * 16;

    for (int m = tid; m < CIN * 8; m += 128) {
        int c = m >> 3, u = m & 7;
        const float* wp = w + (size_t)(obase + 2 * u) * CIN + c;
        ws[m] = pack2(wp[0], wp[CIN]);
    }
    if (tid < 16) bs[tid] = bias[obase + tid];
    __syncthreads();

    int p0 = quarter * 256 + tid;
    const float* zp = zin + (size_t)b * CIN * HW + p0;

    unsigned long long acc[8][2];
    #pragma unroll
    for (int u = 0; u < 8; u++) { acc[u][0] = 0ULL; acc[u][1] = 0ULL; }

    float zn[2][8];
    #pragma unroll
    for (int j = 0; j < 2; j++)
        #pragma unroll
        for (int i = 0; i < 8; i++)
            zn[j][i] = zp[(size_t)i * HW + 128 * j];

    const ulonglong2* ws2 = (const ulonglong2*)ws;
    for (int ch = 0; ch < 32; ch++) {
        float zc[2][8];
        #pragma unroll
        for (int j = 0; j < 2; j++)
            #pragma unroll
            for (int i = 0; i < 8; i++) zc[j][i] = zn[j][i];
        if (ch < 31) {
            #pragma unroll
            for (int j = 0; j < 2; j++)
                #pragma unroll
                for (int i = 0; i < 8; i++)
                    zn[j][i] = zp[(size_t)((ch + 1) * 8 + i) * HW + 128 * j];
        }
        #pragma unroll
        for (int cc = 0; cc < 8; cc++) {
            int c = ch * 8 + cc;
            unsigned long long zz0 = dupf(zc[0][cc]);
            unsigned long long zz1 = dupf(zc[1][cc]);
            const ulonglong2* wrow = ws2 + c * 4;
            #pragma unroll
            for (int uu = 0; uu < 4; uu++) {
                ulonglong2 wp = wrow[uu];
                fma2(acc[2*uu][0],     zz0, wp.x);
                fma2(acc[2*uu][1],     zz1, wp.x);
                fma2(acc[2*uu + 1][0], zz0, wp.y);
                fma2(acc[2*uu + 1][1], zz1, wp.y);
            }
        }
    }

    float* zo = g_z + (size_t)b * COUT * HW;
    #pragma unroll
    for (int u = 0; u < 8; u++) {
        int o = obase + 2 * u;
        #pragma unroll
        for (int j = 0; j < 2; j++) {
            float lo, hi;
            unpack2(lo, hi, acc[u][j]);
            zo[(size_t)o * HW + p0 + 128 * j]       = lo + bs[2*u];
            zo[(size_t)(o + 1) * HW + p0 + 128 * j] = hi + bs[2*u + 1];
        }
    }
}

// ============================================================
// K2: fused distance+argmin + scatter + loss (last-block finalize).
// 7 rows x 4 code-pairs per thread, 112 rows/block, grid 293,
// double-buffered e tiles. Packed f32x2 eval (bit-identical per lane):
// d_j = fl( fl(Sz+Se_j) - 2*dot_j ), dot = in-order 64-term FMA chain.
// ============================================================
__global__ void __launch_bounds__(256, 2) k_argmin(float* __restrict__ out,
                                                   const float* __restrict__ emb) {
    extern __shared__ __align__(16) char smem[];
    float4* zs4  = (float4*)smem;                  // [112][17]
    float4* es4  = zs4 + ZS_F4;                    // [2][64 pair-rows][33]
    float*  Sz_s = (float*)(es4 + 2 * ES_F4);      // [112]
    float*  se_s = Sz_s + ROWS_BLK;                // [2][128]
    float*  red  = se_s + 256;                     // [256]
    __shared__ int    is_last;
    __shared__ double rd[256];
    __shared__ float  sv[EDIM];

    int tid = threadIdx.x;
    int s   = tid & 15;                            // code sublane 0..15
    int g   = tid >> 4;                            // row group 0..15
    int row0 = blockIdx.x * ROWS_BLK;

    // stage z rows (clamped for last block) + e tile 0 + se tile 0
    {
        const float4* zall = (const float4*)g_z;
        #pragma unroll
        for (int j = 0; j < RPT; j++) {
            int idx = tid + 256 * j;
            int r = idx >> 4, k4 = idx & 15;
            int grow = row0 + r;
            if (grow > NROWS - 1) grow = NROWS - 1;
            zs4[r * 17 + k4] = zall[(size_t)grow * 16 + k4];
        }
        const float4* src = (const float4*)g_embi;
        #pragma unroll
        for (int j = 0; j < 8; j++) {
            int idx = tid + 256 * j;
            int pr = idx >> 5, wv = idx & 31;
            es4[pr * 33 + wv] = src[idx];
        }
        if (tid < CODE_TILE) se_s[tid] = g_se[tid];
    }
    __syncthreads();
    if (tid < ROWS_BLK)
        Sz_s[tid] = sumsq64_p(zs4 + tid * 17);
    __syncthreads();

    float best[RPT];
    int   bi[RPT];
    #pragma unroll
    for (int i = 0; i < RPT; i++) { best[i] = 3.4e38f; bi[i] = 0; }

    const float4* gsrc = (const float4*)g_embi;
    const float2* zb = ((const float2*)zs4) + g * 34;
    const unsigned long long m2 = dupf(-2.0f);

    for (int t = 0; t < TILES; t++) {
        int cur = t & 1, nxt = 1 - cur;

        if (t + 1 < TILES) {
            const float4* src = gsrc + (size_t)(t + 1) * 2048;
            #pragma unroll
            for (int j = 0; j < 8; j++) {
                int idx = tid + 256 * j;
                int pr = idx >> 5, wv = idx & 31;
                es4[nxt * ES_F4 + pr * 33 + wv] = src[idx];
            }
            if (tid < CODE_TILE)
                se_s[nxt * 128 + tid] = g_se[(t + 1) * CODE_TILE + tid];
        }

        unsigned long long acc[RPT][4];
        #pragma unroll
        for (int i = 0; i < RPT; i++)
            #pragma unroll
            for (int q = 0; q < 4; q++) acc[i][q] = 0ULL;

        const ulonglong2* ebase = ((const ulonglong2*)(es4 + cur * ES_F4)) + s * 33;

        #pragma unroll 4
        for (int k4 = 0; k4 < 16; k4++) {
            unsigned long long zx[RPT], zy[RPT];
            // half A: dims 4k4, 4k4+1
            #pragma unroll
            for (int i = 0; i < RPT; i++) {
                float2 h = zb[544 * i + 2 * k4];
                zx[i] = dupf(h.x); zy[i] = dupf(h.y);
            }
            #pragma unroll
            for (int q = 0; q < 4; q++) {
                ulonglong2 e01 = ebase[q * 528 + 2 * k4];
                #pragma unroll
                for (int i = 0; i < RPT; i++) {
                    fma2(acc[i][q], zx[i], e01.x);
                    fma2(acc[i][q], zy[i], e01.y);
                }
            }
            // half B: dims 4k4+2, 4k4+3
            #pragma unroll
            for (int i = 0; i < RPT; i++) {
                float2 h = zb[544 * i + 2 * k4 + 1];
                zx[i] = dupf(h.x); zy[i] = dupf(h.y);
            }
            #pragma unroll
            for (int q = 0; q < 4; q++) {
                ulonglong2 e23 = ebase[q * 528 + 2 * k4 + 1];
                #pragma unroll
                for (int i = 0; i < RPT; i++) {
                    fma2(acc[i][q], zx[i], e23.x);
                    fma2(acc[i][q], zy[i], e23.y);
                }
            }
        }

        // eval (packed): per row, q ascending -> codes 8s+2q, 8s+2q+1 ascending
        // lane-lo: fl(fl(Sz+se_lo) - 2*dot_lo); lane-hi same — bit-identical
        #pragma unroll
        for (int i = 0; i < RPT; i++) {
            unsigned long long szd = dupf(Sz_s[g + 16 * i]);
            #pragma unroll
            for (int q = 0; q < 4; q++) {
                int jlo = 8 * s + 2 * q;
                unsigned long long se2 =
                    *(const unsigned long long*)(se_s + cur * 128 + jlo);
                unsigned long long d2 = add2(szd, se2);
                fma2(d2, m2, acc[i][q]);
                float dv, dw;
                unpack2(dv, dw, d2);
                if (dv < best[i]) { best[i] = dv; bi[i] = t * CODE_TILE + jlo; }
                if (dw < best[i]) { best[i] = dw; bi[i] = t * CODE_TILE + jlo + 1; }
            }
        }
        __syncthreads();
    }

    // lexicographic merge across the 16 sublanes (per row)
    unsigned m = 0xffffffffu;
    #pragma unroll
    for (int i = 0; i < RPT; i++) {
        float bv = best[i]; int bj = bi[i];
        #pragma unroll
        for (int off = 8; off > 0; off >>= 1) {
            float ob = __shfl_down_sync(m, bv, off, 16);
            int   oi = __shfl_down_sync(m, bj, off, 16);
            if (ob < bv || (ob == bv && oi < bj)) { bv = ob; bj = oi; }
        }
        bj = __shfl_sync(m, bj, 0, 16);
        bi[i] = bj;
    }

    // epilogue per valid row: idx/min_idx/scatter, z_q_st, loss partial
    float lacc = 0.f;
    #pragma unroll
    for (int i = 0; i < RPT; i++) {
        int rl = g + 16 * i;
        int row = row0 + rl;
        if (row < NROWS) {
            int bj = bi[i];
            if (s == 0) {
                g_idx[row] = bj;
                out[MIDX_OFF + row] = (float)bj;
                out[SAMP_OFF + bj] = 1.0f;   // sampled scatter (zeroed by k_conv)
            }
            float4 e = ((const float4*)(emb + (size_t)bj * EDIM))[s];
            float4 z = zs4[rl * 17 + s];
            float dx = e.x - z.x, dy = e.y - z.y, dz = e.z - z.z, dw = e.w - z.w;
            float4 o;
            o.x = z.x + dx; o.y = z.y + dy; o.z = z.z + dz; o.w = z.w + dw;
            ((float4*)(out + ZQ_OFF + (size_t)row * EDIM))[s] = o;
            lacc += dx*dx + dy*dy + dz*dz + dw*dw;
        }
    }
    red[tid] = lacc;
    __syncthreads();
    #pragma unroll
    for (int st = 128; st > 0; st >>= 1) {
        if (tid < st) red[tid] += red[tid + st];
        __syncthreads();
    }
    if (tid == 0) {
        g_loss_part[blockIdx.x] = red[0];
        __threadfence();
        int old = atomicAdd(&g_done, 1);
        is_last = (old == NBLK - 1);
    }
    __syncthreads();

    // last block to finish reduces the loss scalar (fixed order -> deterministic)
    if (is_last) {
        __threadfence();
        double a = (double)g_loss_part[tid];
        if (tid + 256 < NBLK) a += (double)g_loss_part[tid + 256];
        rd[tid] = a;
        if (tid < EDIM) {
            float v = 0.f;
            #pragma unroll
            for (int j = 0; j < 32; j++) v += g_s_part[j * EDIM + tid];
            sv[tid] = v * v;
        }
        __syncthreads();
        #pragma unroll
        for (int st = 128; st > 0; st >>= 1) {
            if (tid < st) rd[tid] += rd[tid + st];
            __syncthreads();
        }
        if (tid == 0) {
            float c = 0.f;
            for (int j = 0; j < EDIM; j++) c += sv[j];
            out[LOSS_OFF] = (float)(1.25 * (rd[0] / (double)ZLEN))
                          + c / ((float)NE * (float)NE);
        }
    }
}

// ============================================================
extern "C" void kernel_launch(void* const* d_in, const int* in_sizes, int n_in,
                              void* d_out, int out_size) {
    const float* z_    = (const float*)d_in[0];
    const float* convw = (const float*)d_in[1];
    const float* convb = (const float*)d_in[2];
    const float* emb   = (const float*)d_in[3];
    float* out = (float*)d_out;

    cudaFuncSetAttribute(k_argmin, cudaFuncAttributeMaxDynamicSharedMemorySize,
                         SMEM_ARGMIN);

    k_conv<<<512, 128>>>(z_, convw, convb, emb, out);
    k_argmin<<<NBLK, 256, SMEM_ARGMIN>>>(out, emb);
}

// round 15
// speedup vs baseline: 1.1964x; 1.0159x over previous
#include <cuda_runtime.h>
#include <math.h>

// ---------------- problem constants ----------------
#define BATCH   32
#define CIN     256
#define COUT    64
#define HW      1024
#define NE      1024
#define EDIM    64
#define NROWS   32768
#define ZLEN    (BATCH*COUT*HW)   // 2097152
#define TILES   8
#define CODE_TILE 128
#define ROWS_BLK 112
#define RPT      7
#define NCONV    256              // conv-role blocks (each = 2 old conv blocks)
#define NBLK     293              // argmin-role blocks
#define GRID     (NCONV + NBLK)   // 549

// output layout (concat, float32): z_q | loss | sampled | min_idx
#define ZQ_OFF   0
#define LOSS_OFF ((size_t)ZLEN)
#define SAMP_OFF ((size_t)ZLEN + 1)
#define MIDX_OFF ((size_t)ZLEN + 1 + NROWS)

// argmin smem: zs4[112*17] | es4[2][64*33] | Sz[112] | se[2][128] | red[256]
#define ZS_F4    (ROWS_BLK * 17)          // 1904
#define ES_F4    (64 * 33)                // 2112 per buffer
#define SMEM_FUSED ((ZS_F4 + 2*ES_F4) * 16 + ROWS_BLK * 4 + 256 * 4 + 256 * 4)

// ---------------- device scratch ----------------
__device__ __align__(16) float g_z[ZLEN];
__device__ int   g_idx[NROWS];
__device__ float g_se[NE];
__device__ float g_loss_part[NBLK];
__device__ float g_s_part[32 * EDIM];
__device__ int   g_done;           // zero-init; reset by is_last each launch
__device__ int   g_convdone[32];   // zero-init; reset by is_last each launch

// ---------------- packed f32x2 helpers (bit-exact per-lane ops) ----------------
__device__ __forceinline__ unsigned long long dupf(float v) {
    unsigned long long r;
    asm("mov.b64 %0, {%1, %1};" : "=l"(r) : "r"(__float_as_uint(v)));
    return r;
}
__device__ __forceinline__ unsigned long long pack2(float a, float b) {
    unsigned long long r;
    asm("mov.b64 %0, {%1, %2};" : "=l"(r) : "r"(__float_as_uint(a)), "r"(__float_as_uint(b)));
    return r;
}
__device__ __forceinline__ void fma2(unsigned long long& d,
                                     unsigned long long a, unsigned long long b) {
    asm("fma.rn.f32x2 %0, %1, %2, %0;" : "+l"(d) : "l"(a), "l"(b));
}
__device__ __forceinline__ unsigned long long add2(unsigned long long a,
                                                   unsigned long long b) {
    unsigned long long d;
    asm("add.rn.f32x2 %0, %1, %2;" : "=l"(d) : "l"(a), "l"(b));
    return d;
}
__device__ __forceinline__ void unpack2(float& lo, float& hi, unsigned long long v) {
    asm("mov.b64 {%0, %1}, %2;" : "=f"(lo), "=f"(hi) : "l"(v));
}

// Replicated XLA-CPU reduce order: VF=4, IC=2, fmla, faddp-adjacent horizontal.
__device__ __forceinline__ float sumsq64_p(const float4* v4) {
    float a0=0.f,a1=0.f,a2=0.f,a3=0.f, b0=0.f,b1=0.f,b2=0.f,b3=0.f;
    #pragma unroll
    for (int t = 0; t < 8; t++) {
        float4 x = v4[2*t];
        a0 = __fmaf_rn(x.x, x.x, a0); a1 = __fmaf_rn(x.y, x.y, a1);
        a2 = __fmaf_rn(x.z, x.z, a2); a3 = __fmaf_rn(x.w, x.w, a3);
        float4 y = v4[2*t+1];
        b0 = __fmaf_rn(y.x, y.x, b0); b1 = __fmaf_rn(y.y, y.y, b1);
        b2 = __fmaf_rn(y.z, y.z, b2); b3 = __fmaf_rn(y.w, y.w, b3);
    }
    float L0 = a0 + b0, L1 = a1 + b1, L2 = a2 + b2, L3 = a3 + b3;
    return (L0 + L1) + (L2 + L3);
}

// Gather one float4 of the pair-interleaved e-tile straight from emb.
// tile-local idx in [0,2048): pr = idx>>5 (pair-row q*16+sl), wv = idx&31.
// codes (jlo, jlo+1) = (tile*128 + 8*sl + 2*q, +1).
__device__ __forceinline__ float4 gather_e(const float* __restrict__ emb,
                                           int tile, int idx) {
    int pr = idx >> 5, wv = idx & 31;
    int q = pr >> 4, sl = pr & 15;
    int jlo = tile * 128 + 8 * sl + 2 * q;
    const float2* e2 = (const float2*)emb;
    float2 a = e2[jlo * 32 + wv];
    float2 b = e2[(jlo + 1) * 32 + wv];
    return make_float4(a.x, b.x, a.y, b.y);
}

// ============================================================
// Fused kernel. blk < 256: conv role (2 old conv blocks per block,
// plus norms/contrastive/sampled-zero on low blocks); releases
// g_convdone[batch]. blk >= 256: argmin role, spins on its batches.
// All FP chains identical to the 2-kernel version (bit-exact).
// ============================================================
__global__ void __launch_bounds__(256, 2) k_fused(const float* __restrict__ zin,
                                                  const float* __restrict__ w,
                                                  const float* __restrict__ bias,
                                                  const float* __restrict__ emb,
                                                  float* __restrict__ out) {
    extern __shared__ __align__(16) char smem[];
    int tid = threadIdx.x;
    int blk = blockIdx.x;

    if (blk < NCONV) {
        // ================= conv role =================
        unsigned long long* ws = (unsigned long long*)smem;   // [2][2048]
        float* bs = (float*)(ws + 4096);                      // [2][16]
        __shared__ float inv_n[32];
        __shared__ float sq[4][EDIM];

        int half = tid >> 7, tc = tid & 127;
        int co = 2 * blk + half;
        int b = co >> 4, quarter = (co >> 2) & 3, og = co & 3;
        int obase = og * 16;

        // zero 'sampled' region (blocks 0..7)
        if (blk < 8) {
            #pragma unroll
            for (int i = 0; i < 16; i++)
                out[SAMP_OFF + blk * 4096 + tid + 256 * i] = 0.0f;
        }

        // norms + g_se + contrastive partials (blocks 0..31 = batches 0..3)
        if (blk < 32) {
            if (tid < 32) {
                int i = blk * 32 + tid;
                float v = sumsq64_p((const float4*)(emb + (size_t)i * EDIM));
                g_se[i] = v;
                inv_n[tid] = 1.0f / sqrtf(v);
            }
            __syncthreads();
            int k = tid & 63, q = tid >> 6;       // q in 0..3
            float sacc = 0.f;
            #pragma unroll
            for (int i = 0; i < 8; i++) {
                int code = q * 8 + i;
                sacc += emb[(size_t)(blk * 32 + code) * EDIM + k] * inv_n[code];
            }
            sq[q][k] = sacc;
            __syncthreads();
            if (tid < EDIM)
                g_s_part[blk * EDIM + tid] =
                    (sq[0][tid] + sq[1][tid]) + (sq[2][tid] + sq[3][tid]);
        }

        // weights (each half loads its own 16KB)
        unsigned long long* wsh = ws + half * 2048;
        for (int m = tc; m < CIN * 8; m += 128) {
            int c = m >> 3, u = m & 7;
            const float* wp = w + (size_t)(obase + 2 * u) * CIN + c;
            wsh[m] = pack2(wp[0], wp[CIN]);
        }
        if (tc < 16) bs[half * 16 + tc] = bias[obase + tc];
        __syncthreads();

        int p0 = quarter * 256 + tc;
        const float* zp = zin + (size_t)b * CIN * HW + p0;

        unsigned long long acc[8][2];
        #pragma unroll
        for (int u = 0; u < 8; u++) { acc[u][0] = 0ULL; acc[u][1] = 0ULL; }

        float zn[2][8];
        #pragma unroll
        for (int j = 0; j < 2; j++)
            #pragma unroll
            for (int i = 0; i < 8; i++)
                zn[j][i] = zp[(size_t)i * HW + 128 * j];

        const ulonglong2* ws2 = (const ulonglong2*)wsh;
        for (int ch = 0; ch < 32; ch++) {
            float zc[2][8];
            #pragma unroll
            for (int j = 0; j < 2; j++)
                #pragma unroll
                for (int i = 0; i < 8; i++) zc[j][i] = zn[j][i];
            if (ch < 31) {
                #pragma unroll
                for (int j = 0; j < 2; j++)
                    #pragma unroll
                    for (int i = 0; i < 8; i++)
                        zn[j][i] = zp[(size_t)((ch + 1) * 8 + i) * HW + 128 * j];
            }
            #pragma unroll
            for (int cc = 0; cc < 8; cc++) {
                int c = ch * 8 + cc;
                unsigned long long zz0 = dupf(zc[0][cc]);
                unsigned long long zz1 = dupf(zc[1][cc]);
                const ulonglong2* wrow = ws2 + c * 4;
                #pragma unroll
                for (int uu = 0; uu < 4; uu++) {
                    ulonglong2 wp = wrow[uu];
                    fma2(acc[2*uu][0],     zz0, wp.x);
                    fma2(acc[2*uu][1],     zz1, wp.x);
                    fma2(acc[2*uu + 1][0], zz0, wp.y);
                    fma2(acc[2*uu + 1][1], zz1, wp.y);
                }
            }
        }

        float* zo = g_z + (size_t)b * COUT * HW;
        #pragma unroll
        for (int u = 0; u < 8; u++) {
            int o = obase + 2 * u;
            #pragma unroll
            for (int j = 0; j < 2; j++) {
                float lo, hi;
                unpack2(lo, hi, acc[u][j]);
                zo[(size_t)o * HW + p0 + 128 * j]       = lo + bs[half*16 + 2*u];
                zo[(size_t)(o + 1) * HW + p0 + 128 * j] = hi + bs[half*16 + 2*u + 1];
            }
        }

        // release: this batch's conv slice done (8 fused blocks per batch)
        __syncthreads();
        __threadfence();
        if (tid == 0) atomicAdd(&g_convdone[b], 1);
        return;
    }

    // ================= argmin role =================
    int ablk = blk - NCONV;
    float4* zs4  = (float4*)smem;                  // [112][17]
    float4* es4  = zs4 + ZS_F4;                    // [2][64 pair-rows][33]
    float*  Sz_s = (float*)(es4 + 2 * ES_F4);      // [112]
    float*  se_s = Sz_s + ROWS_BLK;                // [2][128]
    float*  red  = se_s + 256;                     // [256]
    __shared__ int    is_last;
    __shared__ double rd[256];
    __shared__ float  sv[EDIM];

    int s   = tid & 15;
    int g   = tid >> 4;
    int row0 = ablk * ROWS_BLK;

    // spin until producers done: batches 0..3 (norms/g_se/sampled-zero
    // live in conv blocks 0..31) + this block's own batch(es)
    if (tid == 0) {
        int b0 = row0 / 1024;
        int b1 = (row0 + ROWS_BLK - 1 < NROWS ? row0 + ROWS_BLK - 1 : NROWS - 1) / 1024;
        #pragma unroll
        for (int bb = 0; bb < 4; bb++)
            while (atomicAdd(&g_convdone[bb], 0) < 8) __nanosleep(128);
        while (atomicAdd(&g_convdone[b0], 0) < 8) __nanosleep(128);
        while (atomicAdd(&g_convdone[b1], 0) < 8) __nanosleep(128);
        __threadfence();
    }
    __syncthreads();

    // stage z rows (clamped for last block) + e tile 0 (gather) + se tile 0
    {
        const float4* zall = (const float4*)g_z;
        #pragma unroll
        for (int j = 0; j < RPT; j++) {
            int idx = tid + 256 * j;
            int r = idx >> 4, k4 = idx & 15;
            int grow = row0 + r;
            if (grow > NROWS - 1) grow = NROWS - 1;
            zs4[r * 17 + k4] = zall[(size_t)grow * 16 + k4];
        }
        #pragma unroll
        for (int j = 0; j < 8; j++) {
            int idx = tid + 256 * j;
            int pr = idx >> 5, wv = idx & 31;
            es4[pr * 33 + wv] = gather_e(emb, 0, idx);
        }
        if (tid < CODE_TILE) se_s[tid] = g_se[tid];
    }
    __syncthreads();
    if (tid < ROWS_BLK)
        Sz_s[tid] = sumsq64_p(zs4 + tid * 17);
    __syncthreads();

    float best[RPT];
    int   bi[RPT];
    #pragma unroll
    for (int i = 0; i < RPT; i++) { best[i] = 3.4e38f; bi[i] = 0; }

    const float2* zb = ((const float2*)zs4) + g * 34;
    const unsigned long long m2 = dupf(-2.0f);

    for (int t = 0; t < TILES; t++) {
        int cur = t & 1, nxt = 1 - cur;

        if (t + 1 < TILES) {
            #pragma unroll
            for (int j = 0; j < 8; j++) {
                int idx = tid + 256 * j;
                int pr = idx >> 5, wv = idx & 31;
                es4[nxt * ES_F4 + pr * 33 + wv] = gather_e(emb, t + 1, idx);
            }
            if (tid < CODE_TILE)
                se_s[nxt * 128 + tid] = g_se[(t + 1) * CODE_TILE + tid];
        }

        unsigned long long acc[RPT][4];
        #pragma unroll
        for (int i = 0; i < RPT; i++)
            #pragma unroll
            for (int q = 0; q < 4; q++) acc[i][q] = 0ULL;

        const ulonglong2* ebase = ((const ulonglong2*)(es4 + cur * ES_F4)) + s * 33;

        #pragma unroll 4
        for (int k4 = 0; k4 < 16; k4++) {
            unsigned long long zx[RPT], zy[RPT];
            // half A: dims 4k4, 4k4+1
            #pragma unroll
            for (int i = 0; i < RPT; i++) {
                float2 h = zb[544 * i + 2 * k4];
                zx[i] = dupf(h.x); zy[i] = dupf(h.y);
            }
            #pragma unroll
            for (int q = 0; q < 4; q++) {
                ulonglong2 e01 = ebase[q * 528 + 2 * k4];
                #pragma unroll
                for (int i = 0; i < RPT; i++) {
                    fma2(acc[i][q], zx[i], e01.x);
                    fma2(acc[i][q], zy[i], e01.y);
                }
            }
            // half B: dims 4k4+2, 4k4+3
            #pragma unroll
            for (int i = 0; i < RPT; i++) {
                float2 h = zb[544 * i + 2 * k4 + 1];
                zx[i] = dupf(h.x); zy[i] = dupf(h.y);
            }
            #pragma unroll
            for (int q = 0; q < 4; q++) {
                ulonglong2 e23 = ebase[q * 528 + 2 * k4 + 1];
                #pragma unroll
                for (int i = 0; i < RPT; i++) {
                    fma2(acc[i][q], zx[i], e23.x);
                    fma2(acc[i][q], zy[i], e23.y);
                }
            }
        }

        // eval (packed): per row, q ascending -> codes 8s+2q, 8s+2q+1 ascending
        #pragma unroll
        for (int i = 0; i < RPT; i++) {
            unsigned long long szd = dupf(Sz_s[g + 16 * i]);
            #pragma unroll
            for (int q = 0; q < 4; q++) {
                int jlo = 8 * s + 2 * q;
                unsigned long long se2 =
                    *(const unsigned long long*)(se_s + cur * 128 + jlo);
                unsigned long long d2 = add2(szd, se2);
                fma2(d2, m2, acc[i][q]);
                float dv, dw;
                unpack2(dv, dw, d2);
                if (dv < best[i]) { best[i] = dv; bi[i] = t * CODE_TILE + jlo; }
                if (dw < best[i]) { best[i] = dw; bi[i] = t * CODE_TILE + jlo + 1; }
            }
        }
        __syncthreads();
    }

    // lexicographic merge across the 16 sublanes (per row)
    unsigned m = 0xffffffffu;
    #pragma unroll
    for (int i = 0; i < RPT; i++) {
        float bv = best[i]; int bj = bi[i];
        #pragma unroll
        for (int off = 8; off > 0; off >>= 1) {
            float ob = __shfl_down_sync(m, bv, off, 16);
            int   oi = __shfl_down_sync(m, bj, off, 16);
            if (ob < bv || (ob == bv && oi < bj)) { bv = ob; bj = oi; }
        }
        bj = __shfl_sync(m, bj, 0, 16);
        bi[i] = bj;
    }

    // epilogue per valid row: idx/min_idx/scatter, z_q_st, loss partial
    float lacc = 0.f;
    #pragma unroll
    for (int i = 0; i < RPT; i++) {
        int rl = g + 16 * i;
        int row = row0 + rl;
        if (row < NROWS) {
            int bj = bi[i];
            if (s == 0) {
                g_idx[row] = bj;
                out[MIDX_OFF + row] = (float)bj;
                out[SAMP_OFF + bj] = 1.0f;
            }
            float4 e = ((const float4*)(emb + (size_t)bj * EDIM))[s];
            float4 z = zs4[rl * 17 + s];
            float dx = e.x - z.x, dy = e.y - z.y, dz = e.z - z.z, dw = e.w - z.w;
            float4 o;
            o.x = z.x + dx; o.y = z.y + dy; o.z = z.z + dz; o.w = z.w + dw;
            ((float4*)(out + ZQ_OFF + (size_t)row * EDIM))[s] = o;
            lacc += dx*dx + dy*dy + dz*dz + dw*dw;
        }
    }
    red[tid] = lacc;
    __syncthreads();
    #pragma unroll
    for (int st = 128; st > 0; st >>= 1) {
        if (tid < st) red[tid] += red[tid + st];
        __syncthreads();
    }
    if (tid == 0) {
        g_loss_part[ablk] = red[0];
        __threadfence();
        int old = atomicAdd(&g_done, 1);
        is_last = (old == NBLK - 1);
    }
    __syncthreads();

    // last argmin block: finalize loss + reset counters for next launch
    if (is_last) {
        __threadfence();
        double a = (double)g_loss_part[tid];
        if (tid + 256 < NBLK) a += (double)g_loss_part[tid + 256];
        rd[tid] = a;
        if (tid < EDIM) {
            float v = 0.f;
            #pragma unroll
            for (int j = 0; j < 32; j++) v += g_s_part[j * EDIM + tid];
            sv[tid] = v * v;
        }
        __syncthreads();
        #pragma unroll
        for (int st = 128; st > 0; st >>= 1) {
            if (tid < st) rd[tid] += rd[tid + st];
            __syncthreads();
        }
        if (tid == 0) {
            float c = 0.f;
            for (int j = 0; j < EDIM; j++) c += sv[j];
            out[LOSS_OFF] = (float)(1.25 * (rd[0] / (double)ZLEN))
                          + c / ((float)NE * (float)NE);
            g_done = 0;
        }
        if (tid < 32) g_convdone[tid] = 0;
    }
}

// ============================================================
extern "C" void kernel_launch(void* const* d_in, const int* in_sizes, int n_in,
                              void* d_out, int out_size) {
    const float* z_    = (const float*)d_in[0];
    const float* convw = (const float*)d_in[1];
    const float* convb = (const float*)d_in[2];
    const float* emb   = (const float*)d_in[3];
    float* out = (float*)d_out;

    cudaFuncSetAttribute(k_fused, cudaFuncAttributeMaxDynamicSharedMemorySize,
                         SMEM_FUSED);

    k_fused<<<GRID, 256, SMEM_FUSED>>>(z_, convw, convb, emb, out);
}